// round 14
// baseline (speedup 1.0000x reference)
#include <cuda_runtime.h>
#include <math.h>
#include <stdint.h>

// Problem constants
#define LSC   2
#define BSC   16
#define NHC   256
#define NPARTC 512
#define MIDP  256
#define TTC   16
#define DINC  64
#define FHC   1024

// Output layout: tuple (W_mu(16,1), sig(16,1,1), pf(2,16,256,512), wf(16,512), l, nis)
#define OFF_WMU 0
#define OFF_SIG 16
#define OFF_PF  32
#define OFF_WF  (32 + LSC*BSC*NHC*NPARTC)
#define OFF_L   (OFF_WF + BSC*NPARTC)
#define OFF_NIS (OFF_L + 1)

// ---- tiny globals only (33 KB, proven-safe config) --------------------------
__device__ int g_idx[BSC*2*MIDP];
__device__ int g_do[BSC*2];

__device__ __forceinline__ float sigf(float x)   { return 1.0f/(1.0f+__expf(-x)); }
__device__ __forceinline__ float tanhfa(float x) { return 2.0f/(1.0f+__expf(-2.0f*x)) - 1.0f; }
__device__ __forceinline__ float f4c(const float4 v, int i){
    return (i==0) ? v.x : (i==1) ? v.y : (i==2) ? v.z : v.w;
}
__device__ __forceinline__ uint32_t f2tf(float x){
    uint32_t r; asm("cvt.rna.tf32.f32 %0, %1;" : "=r"(r) : "f"(x)); return r;
}
__device__ __forceinline__ void mma_tf32(float4& d, uint32_t a0, uint32_t a1,
                                         uint32_t a2, uint32_t a3,
                                         uint32_t b0, uint32_t b1){
    asm volatile("mma.sync.aligned.m16n8k8.row.col.f32.tf32.tf32.f32 "
        "{%0,%1,%2,%3}, {%4,%5,%6,%7}, {%8,%9}, {%0,%1,%2,%3};"
        : "+f"(d.x), "+f"(d.y), "+f"(d.z), "+f"(d.w)
        : "r"(a0), "r"(a1), "r"(a2), "r"(a3), "r"(b0), "r"(b1));
}

__device__ __forceinline__ float bsum(float* red, int tid, int nthr, float v){
    red[tid]=v; __syncthreads();
    for (int s=nthr>>1; s>0; s>>=1){ if(tid<s) red[tid]+=red[tid+s]; __syncthreads(); }
    float r = red[0]; __syncthreads(); return r;
}
__device__ __forceinline__ float bmax(float* red, int tid, int nthr, float v){
    red[tid]=v; __syncthreads();
    for (int s=nthr>>1; s>0; s>>=1){ if(tid<s) red[tid]=fmaxf(red[tid],red[tid+s]); __syncthreads(); }
    float r = red[0]; __syncthreads(); return r;
}

// =============================================================================
// Persistent LSTM kernel, tensor-core (3xTF32) mainloop.
// 128 CTAs x 256 threads. CTA = (batch b, particles p0..p0+31).
// Gates G[32][1024] = H[32][K] @ W^T via mma.sync m16n8k8 tf32 (hi/lo split).
// smem floats:
//   H0: 0      (32 x 260)  8320      H1: 8320   (8320)
//   C0: 16640  (8320)                C1: 24960  (8320)
//   WThi: 33280 (8 x 1032 = 8256)    WTlo: 41536 (8256)
//   XWV: 49792 (1024)  B1P: 50816 (1024)  XR: 51840 (64)
//   total 51904 floats = 207616 bytes
// =============================================================================
#define HS    260
#define WTS   1032
#define SMEM_FLOATS 51904
#define SMEM_BYTES  (SMEM_FLOATS*4)

__global__ __launch_bounds__(256)
void k_lstm(const float* __restrict__ x, const float* __restrict__ particles,
            const float* __restrict__ q, const float* __restrict__ e,
            const float* __restrict__ Wih0, const float* __restrict__ Whh0,
            const float* __restrict__ b0,
            const float* __restrict__ Wih1, const float* __restrict__ Whh1,
            const float* __restrict__ b1,
            const float* __restrict__ eps_h, const float* __restrict__ eps_c,
            float* __restrict__ pf){
    extern __shared__ __align__(16) float sm[];
    float* H0   = sm;
    float* H1   = sm + 8320;
    float* C0   = sm + 16640;
    float* C1   = sm + 24960;
    float* WThi = sm + 33280;
    float* WTlo = sm + 41536;
    float* XWV  = sm + 49792;
    float* B1P  = sm + 50816;
    float* XR   = sm + 51840;

    int tid  = threadIdx.x;
    int lane = tid & 31;
    int warp = tid >> 5;            // 0..7, owns N-tiles warp*16..warp*16+15
    int r = lane >> 2;              // fragment row 0..7
    int c = lane & 3;               // fragment col 0..3
    int blk = blockIdx.x;
    int b  = blk >> 3;
    int p0 = (blk & 7) * 32;

    // ---- init: load particle states (stride-260 layout) ----
    for (int idx = tid; idx < 8192; idx += 256){
        int row = idx >> 8, u = idx & 255; int p = p0 + row;
        size_t base0 = ((size_t)(0*BSC + b)*NHC + u)*NPARTC;
        size_t base1 = ((size_t)(1*BSC + b)*NHC + u)*NPARTC;
        H0[row*HS + u] = particles[base0 + p];
        H1[row*HS + u] = particles[base1 + p];
        C0[row*HS + u] = particles[base0 + MIDP + p];
        C1[row*HS + u] = particles[base1 + MIDP + p];
    }
    for (int jp = tid; jp < 1024; jp += 256){
        int jo = ((jp & 3) << 8) | (jp >> 2);
        B1P[jp] = b1[jo];
    }
    __syncthreads();

    // ---- time loop ----
    for (int t = 0; t < TTC; t++){
        if (tid < 64) XR[tid] = x[(b*TTC + t)*DINC + tid];
        __syncthreads();
        // input projection (permuted j' = 4u+gate), float4-vectorized
        for (int jp = tid; jp < 1024; jp += 256){
            int jo = ((jp & 3) << 8) | (jp >> 2);
            const float4* wr = reinterpret_cast<const float4*>(Wih0 + jo*DINC);
            const float4* xr = reinterpret_cast<const float4*>(XR);
            float acc = b0[jo];
            #pragma unroll
            for (int k4 = 0; k4 < DINC/4; k4++){
                float4 wv = wr[k4]; float4 xv = xr[k4];
                acc = fmaf(xv.x, wv.x, acc);
                acc = fmaf(xv.y, wv.y, acc);
                acc = fmaf(xv.z, wv.z, acc);
                acc = fmaf(xv.w, wv.w, acc);
            }
            XWV[jp] = acc;
        }
        // (XWV consumed by epilogue; ordering ensured by mainloop barriers)

        for (int layer = 0; layer < 2; layer++){
            const float* Wlo_m = (layer==0) ? Whh0 : Wih1;   // k < 256
            const float* Whi_m = Whh1;                        // k >= 256 (layer1)
            float* Hs = (layer==0) ? H0 : H1;
            float* Cs = (layer==0) ? C0 : C1;
            const float* pre = (layer==0) ? XWV : B1P;
            int nkt = (layer==0) ? 32 : 64;                   // 8-k steps

            float4 d4[2][16];
            #pragma unroll
            for (int ms=0; ms<2; ms++)
                #pragma unroll
                for (int j=0; j<16; j++) d4[ms][j] = make_float4(0.f,0.f,0.f,0.f);

            for (int kt = 0; kt < nkt; kt++){
                __syncthreads();   // WT buffers free
                // ---- stage weight tile [8k x 1024 j'] as hi/lo, float4-packed
                {
                    const float* Ws = (kt < 32) ? Wlo_m : Whi_m;
                    int k0 = (kt & 31) * 8;
                    float4 va[4][2];
                    #pragma unroll
                    for (int jj=0; jj<4; jj++){
                        const float* wr = Ws + (size_t)(jj*256 + tid)*256 + k0;
                        va[jj][0] = *reinterpret_cast<const float4*>(wr);
                        va[jj][1] = *reinterpret_cast<const float4*>(wr+4);
                    }
                    float4* WThi4 = reinterpret_cast<float4*>(WThi);
                    float4* WTlo4 = reinterpret_cast<float4*>(WTlo);
                    #pragma unroll
                    for (int kk=0; kk<8; kk++){
                        float w0 = f4c(va[0][kk>>2], kk&3);
                        float w1 = f4c(va[1][kk>>2], kk&3);
                        float w2 = f4c(va[2][kk>>2], kk&3);
                        float w3 = f4c(va[3][kk>>2], kk&3);
                        uint32_t h0b=f2tf(w0), h1b=f2tf(w1), h2b=f2tf(w2), h3b=f2tf(w3);
                        float4 hv = make_float4(__uint_as_float(h0b), __uint_as_float(h1b),
                                                __uint_as_float(h2b), __uint_as_float(h3b));
                        float4 lv = make_float4(
                            __uint_as_float(f2tf(w0 - __uint_as_float(h0b))),
                            __uint_as_float(f2tf(w1 - __uint_as_float(h1b))),
                            __uint_as_float(f2tf(w2 - __uint_as_float(h2b))),
                            __uint_as_float(f2tf(w3 - __uint_as_float(h3b))));
                        WThi4[kk*(WTS/4) + tid] = hv;
                        WTlo4[kk*(WTS/4) + tid] = lv;
                    }
                }
                __syncthreads();

                // ---- A fragments (hi/lo) from smem H
                const float* Asrc; int kloc;
                if (layer==0){ Asrc = H0; kloc = kt*8; }
                else if (kt < 32){ Asrc = H0; kloc = kt*8; }
                else { Asrc = H1; kloc = (kt-32)*8; }
                uint32_t ahi[2][4], alo[2][4];
                #pragma unroll
                for (int ms=0; ms<2; ms++){
                    #pragma unroll
                    for (int ii=0; ii<4; ii++){
                        int row = ms*16 + r + ((ii & 1) << 3);
                        int col = kloc + c + ((ii >> 1) << 2);
                        float av = Asrc[row*HS + col];
                        uint32_t hb = f2tf(av);
                        ahi[ms][ii] = hb;
                        alo[ms][ii] = f2tf(av - __uint_as_float(hb));
                    }
                }
                // ---- mma over owned N-tiles
                #pragma unroll
                for (int j=0; j<16; j++){
                    int np = (warp*16 + j)*8 + r;
                    uint32_t bh0 = __float_as_uint(WThi[ c   *WTS + np]);
                    uint32_t bh1 = __float_as_uint(WThi[(c+4)*WTS + np]);
                    uint32_t bl0 = __float_as_uint(WTlo[ c   *WTS + np]);
                    uint32_t bl1 = __float_as_uint(WTlo[(c+4)*WTS + np]);
                    #pragma unroll
                    for (int ms=0; ms<2; ms++){
                        mma_tf32(d4[ms][j], ahi[ms][0],ahi[ms][1],ahi[ms][2],ahi[ms][3], bh0, bh1);
                        mma_tf32(d4[ms][j], ahi[ms][0],ahi[ms][1],ahi[ms][2],ahi[ms][3], bl0, bl1);
                        mma_tf32(d4[ms][j], alo[ms][0],alo[ms][1],alo[ms][2],alo[ms][3], bh0, bh1);
                    }
                }
            }
            __syncthreads();   // all mma reads of H done before in-place update

            // ---- epilogue: add pre-activation, reunite gate quads, cell update
            #pragma unroll
            for (int ms=0; ms<2; ms++){
                #pragma unroll
                for (int j=0; j<16; j++){
                    int nt = warp*16 + j;
                    int jp0 = nt*8 + 2*c;
                    float pz0 = pre[jp0], pz1 = pre[jp0+1];
                    float g0 = d4[ms][j].x + pz0;
                    float g1 = d4[ms][j].y + pz1;
                    float g2 = d4[ms][j].z + pz0;
                    float g3 = d4[ms][j].w + pz1;
                    float e0 = __shfl_xor_sync(0xFFFFFFFFu, g0, 1);
                    float e1 = __shfl_xor_sync(0xFFFFFFFFu, g1, 1);
                    float e2 = __shfl_xor_sync(0xFFFFFFFFu, g2, 1);
                    float e3 = __shfl_xor_sync(0xFFFFFFFFu, g3, 1);
                    if (!(lane & 1)){
                        int u = nt*2 + (c >> 1);
                        int row0 = ms*16 + r;
                        {
                            float cold = Cs[row0*HS + u];
                            float cn = sigf(g1)*cold + sigf(g0)*tanhfa(e0);
                            float hn = sigf(e1)*tanhfa(cn);
                            Cs[row0*HS + u] = cn;
                            Hs[row0*HS + u] = hn;
                        }
                        {
                            float cold = Cs[(row0+8)*HS + u];
                            float cn = sigf(g3)*cold + sigf(g2)*tanhfa(e2);
                            float hn = sigf(e3)*tanhfa(cn);
                            Cs[(row0+8)*HS + u] = cn;
                            Hs[(row0+8)*HS + u] = hn;
                        }
                    }
                }
            }
            __syncthreads();   // H updated before next layer / next t reads
        }
    }

    // ---- write pr = final state + noise into pf (l,b,u,512) ----
    float sq = sqrtf(q[0]*q[0]);
    float se = sqrtf(e[0]*e[0]);
    for (int idx = tid; idx < 8192; idx += 256){
        int row = idx >> 8, u = idx & 255; int p = p0 + row;
        size_t o0 = ((size_t)(0*BSC + b)*NHC + u)*NPARTC;
        size_t o1 = ((size_t)(1*BSC + b)*NHC + u)*NPARTC;
        int e0i = ((p*LSC + 0)*BSC + b)*NHC + u;
        int e1i = ((p*LSC + 1)*BSC + b)*NHC + u;
        pf[o0 + p]        = H0[row*HS+u] + sq*eps_h[e0i];
        pf[o1 + p]        = H1[row*HS+u] + sq*eps_h[e1i];
        pf[o0 + MIDP + p] = C0[row*HS+u] + se*eps_c[e0i];
        pf[o1 + MIDP + p] = C1[row*HS+u] + se*eps_c[e1i];
    }
}

// ---------------- obs + weight update; preW staged into out.wf ---------------
__global__ __launch_bounds__(512)
void k_stats1(const float* __restrict__ weights, const float* __restrict__ y,
              const float* __restrict__ r, const float* __restrict__ pf,
              const float* __restrict__ Wh, const float* __restrict__ bh,
              float* __restrict__ out){
    __shared__ __align__(16) float ws[NHC];
    __shared__ float red[512];
    int b = blockIdx.x; int tid = threadIdx.x;
    if (tid < NHC) ws[tid] = Wh[tid];
    __syncthreads();
    float Yv = bh[0];
    const float* base = pf + ((size_t)(BSC + b)*NHC)*NPARTC;   // l=1
    for (int u=0; u<NHC; u++) Yv = fmaf(ws[u], base[(size_t)u*NPARTC + tid], Yv);
    float w  = logf(weights[b*NPARTC + tid]);
    float wsum = bsum(red, tid, 512, w);
    float s1   = bsum(red, tid, 512, Yv*w);
    float Wmu  = s1 / wsum;
    float cen  = Yv - Wmu;
    float cov  = bsum(red, tid, 512, cen*cen) / (float)(NPARTC-1) + r[0]*r[0];
    float s    = cov + 1e-6f;
    float innov = y[b] - Yv*w/wsum;
    out[OFF_WF + b*NPARTC + tid] = w - 0.5f*logf(s) - 0.5f*innov*innov/s;   // preW
}

// ---- normalize preW across the BATCH axis (reference quirk), in place -------
__global__ __launch_bounds__(512)
void k_norm(float* __restrict__ out){
    int n = threadIdx.x;
    float v[BSC];
    float s = 0.0f;
    #pragma unroll
    for (int b=0;b<BSC;b++){ v[b] = out[OFF_WF + b*NPARTC + n]; s += expf(v[b]); }
    float ls = logf(s);
    #pragma unroll
    for (int b=0;b<BSC;b++) out[OFF_WF + b*NPARTC + n] = expf(v[b] - ls);   // neww
}

// ---------------- per-(batch,half) resample: bitonic argsort of 256 ----------
__global__ __launch_bounds__(256)
void k_resample(const float* __restrict__ gumbel, float* __restrict__ out){
    __shared__ __align__(16) float key[256];
    __shared__ __align__(16) int   idxs[256];
    __shared__ __align__(16) float red[256];
    int blk = blockIdx.x; int b = blk>>1; int half = blk&1; int tid = threadIdx.x;
    float wh = out[OFF_WF + b*NPARTC + half*MIDP + tid];
    float ss = bsum(red, tid, 256, wh*wh);
    int dof = (1.0f/ss < (float)NPARTC/4.0f) ? 1 : 0;
    float soft = 0.5f*wh + 0.5f/(float)MIDP;
    key[tid]  = -(logf(soft) + gumbel[(b*2 + half)*MIDP + tid]);
    idxs[tid] = tid;
    __syncthreads();
    for (int k=2;k<=256;k<<=1){
        for (int j=k>>1;j>0;j>>=1){
            int ixj = tid ^ j;
            if (ixj > tid){
                bool up = ((tid & k) == 0);
                float a = key[tid], bk = key[ixj];
                if ((a > bk) == up){
                    key[tid]=bk; key[ixj]=a;
                    int t0=idxs[tid]; idxs[tid]=idxs[ixj]; idxs[ixj]=t0;
                }
            }
            __syncthreads();
        }
    }
    g_idx[blk*MIDP + tid] = idxs[tid];
    float lw = logf(wh/soft);
    float mx = bmax(red, tid, 256, lw);
    float se = bsum(red, tid, 256, expf(lw-mx));
    float lse = mx + logf(se);
    float wr = expf(lw - lse);
    out[OFF_WF + b*NPARTC + half*MIDP + tid] = dof ? wr : wh;
    if (tid==0) g_do[blk] = dof;
}

// ---------------- in-place gather on pf (per (b,half) permutation) -----------
__global__ __launch_bounds__(256)
void k_gather(float* __restrict__ pf){
    __shared__ __align__(16) float seg[8][256];
    __shared__ int idx_s[256];
    int blk = blockIdx.x;            // b*2+half
    int chunk = blockIdx.y;          // 0..63 -> 8 (l,u) rows each
    int b = blk>>1; int half = blk&1; int tid = threadIdx.x;
    if (!g_do[blk]) return;
    idx_s[tid] = g_idx[blk*MIDP + tid];
    int row0 = chunk*8;
    #pragma unroll
    for (int i=0;i<8;i++){
        int rr = row0 + i;
        int l = rr >> 8, u = rr & 255;
        seg[i][tid] = pf[(((size_t)(l*BSC+b))*NHC + u)*NPARTC + half*MIDP + tid];
    }
    __syncthreads();
    #pragma unroll
    for (int i=0;i<8;i++){
        int rr = row0 + i;
        int l = rr >> 8, u = rr & 255;
        pf[(((size_t)(l*BSC+b))*NHC + u)*NPARTC + half*MIDP + tid] = seg[i][idx_s[tid]];
    }
}

// ---------------- final estimate (obs fused, 16 blocks) ----------------------
__global__ __launch_bounds__(512)
void k_stats2(const float* __restrict__ y, const float* __restrict__ r,
              const float* __restrict__ pf, const float* __restrict__ Wh,
              const float* __restrict__ bh, float* __restrict__ out){
    __shared__ __align__(16) float ws[NHC];
    __shared__ float red[512];
    int b = blockIdx.x; int tid = threadIdx.x;
    if (tid < NHC) ws[tid] = Wh[tid];
    __syncthreads();
    float Yv = bh[0];
    const float* base = pf + ((size_t)(BSC + b)*NHC)*NPARTC;   // l=1
    for (int u=0; u<NHC; u++) Yv = fmaf(ws[u], base[(size_t)u*NPARTC + tid], Yv);
    float wv = out[OFF_WF + b*NPARTC + tid];
    float wsum = bsum(red, tid, 512, wv);
    float Wmu  = bsum(red, tid, 512, Yv*wv) / wsum;
    float cen  = Yv - Wmu;
    float cov  = bsum(red, tid, 512, cen*cen) / (float)(NPARTC-1) + r[0]*r[0];
    if (tid==0){
        out[OFF_WMU + b] = Wmu;
        out[OFF_SIG + b] = cov;
    }
}

// ---- scalars recomputed from already-written W_mu/sig -----------------------
__global__ __launch_bounds__(32)
void k_scalars(const float* __restrict__ y, float* __restrict__ out){
    if (threadIdx.x != 0) return;
    float l = 0.0f, nq = 0.0f;
    for (int b=0;b<BSC;b++){
        float s = out[OFF_SIG + b] + 1e-6f;
        float inn = y[b] - out[OFF_WMU + b];
        float qf = inn*inn/s;
        l += -0.5f*logf(s) - 0.5f*qf;
        nq += qf;
    }
    out[OFF_L]   = l;
    out[OFF_NIS] = nq / (float)BSC;
}

// =============================================================================
extern "C" void kernel_launch(void* const* d_in, const int* in_sizes, int n_in,
                              void* d_out, int out_size){
    const float* x        = (const float*)d_in[0];
    const float* y        = (const float*)d_in[1];
    const float* particles= (const float*)d_in[2];
    const float* weights  = (const float*)d_in[3];
    const float* q        = (const float*)d_in[4];
    const float* e        = (const float*)d_in[5];
    const float* r        = (const float*)d_in[6];
    const float* Wih0     = (const float*)d_in[7];
    const float* Whh0     = (const float*)d_in[8];
    const float* b0       = (const float*)d_in[9];
    const float* Wih1     = (const float*)d_in[10];
    const float* Whh1     = (const float*)d_in[11];
    const float* b1       = (const float*)d_in[12];
    const float* Wh       = (const float*)d_in[13];
    const float* bh       = (const float*)d_in[14];
    const float* eps_h    = (const float*)d_in[15];
    const float* eps_c    = (const float*)d_in[16];
    const float* gumbel   = (const float*)d_in[17];
    float* out = (float*)d_out;
    float* pf  = out + OFF_PF;

    static bool attr_set = false;
    if (!attr_set){
        cudaFuncSetAttribute(k_lstm, cudaFuncAttributeMaxDynamicSharedMemorySize, SMEM_BYTES);
        attr_set = true;
    }

    // 1. full recurrence (tensor-core 3xTF32 mainloop); writes pr into pf
    k_lstm<<<128, 256, SMEM_BYTES>>>(x, particles, q, e,
                                     Wih0, Whh0, b0, Wih1, Whh1, b1,
                                     eps_h, eps_c, pf);
    // 2. obs + weight update (preW -> out.wf), batch-axis norm in place
    k_stats1<<<BSC, 512>>>(weights, y, r, pf, Wh, bh, out);
    k_norm<<<1, 512>>>(out);
    // 3. resample halves (reads neww from out.wf, writes final wf + g_idx/g_do)
    k_resample<<<BSC*2, 256>>>(gumbel, out);
    // 4. in-place gather pr -> pf
    k_gather<<<dim3(BSC*2, 64), 256>>>(pf);
    // 5. final obs + estimate, then scalars
    k_stats2<<<BSC, 512>>>(y, r, pf, Wh, bh, out);
    k_scalars<<<1, 32>>>(y, out);
}

// round 15
// speedup vs baseline: 1.2546x; 1.2546x over previous
#include <cuda_runtime.h>
#include <math.h>
#include <stdint.h>

// Problem constants
#define LSC   2
#define BSC   16
#define NHC   256
#define NPARTC 512
#define MIDP  256
#define TTC   16
#define DINC  64
#define FHC   1024

// Output layout: tuple (W_mu(16,1), sig(16,1,1), pf(2,16,256,512), wf(16,512), l, nis)
#define OFF_WMU 0
#define OFF_SIG 16
#define OFF_PF  32
#define OFF_WF  (32 + LSC*BSC*NHC*NPARTC)
#define OFF_L   (OFF_WF + BSC*NPARTC)
#define OFF_NIS (OFF_L + 1)

// ---- tiny globals only (33 KB, proven-safe config) --------------------------
__device__ int g_idx[BSC*2*MIDP];
__device__ int g_do[BSC*2];

__device__ __forceinline__ float sigf(float x)   { return 1.0f/(1.0f+__expf(-x)); }
__device__ __forceinline__ float tanhfa(float x) { return 2.0f/(1.0f+__expf(-2.0f*x)) - 1.0f; }
__device__ __forceinline__ uint32_t f2tf(float x){
    uint32_t r; asm("cvt.rna.tf32.f32 %0, %1;" : "=r"(r) : "f"(x)); return r;
}
__device__ __forceinline__ void mma_tf32(float4& d, uint32_t a0, uint32_t a1,
                                         uint32_t a2, uint32_t a3,
                                         uint32_t b0, uint32_t b1){
    asm volatile("mma.sync.aligned.m16n8k8.row.col.f32.tf32.tf32.f32 "
        "{%0,%1,%2,%3}, {%4,%5,%6,%7}, {%8,%9}, {%0,%1,%2,%3};"
        : "+f"(d.x), "+f"(d.y), "+f"(d.z), "+f"(d.w)
        : "r"(a0), "r"(a1), "r"(a2), "r"(a3), "r"(b0), "r"(b1));
}
__device__ __forceinline__ void cp16(uint32_t dst, const void* src){
    asm volatile("cp.async.ca.shared.global [%0], [%1], 16;" :: "r"(dst), "l"(src));
}

__device__ __forceinline__ float bsum(float* red, int tid, int nthr, float v){
    red[tid]=v; __syncthreads();
    for (int s=nthr>>1; s>0; s>>=1){ if(tid<s) red[tid]+=red[tid+s]; __syncthreads(); }
    float r = red[0]; __syncthreads(); return r;
}
__device__ __forceinline__ float bmax(float* red, int tid, int nthr, float v){
    red[tid]=v; __syncthreads();
    for (int s=nthr>>1; s>0; s>>=1){ if(tid<s) red[tid]=fmaxf(red[tid],red[tid+s]); __syncthreads(); }
    float r = red[0]; __syncthreads(); return r;
}

// =============================================================================
// Persistent LSTM kernel, tensor-core (3xTF32) mainloop, cp.async staging.
// 128 CTAs x 256 threads. CTA = (batch b, particles p0..p0+31).
// Gates G[32][1024] = H[32][K] @ W^T via mma.sync m16n8k8 tf32 (hi/lo split,
// conversion on the consumer side). Weight tiles [1024 j' x 8k] staged RAW
// with cp.async (row-pair coalesced, XOR-swizzled), double buffered.
// smem floats:
//   H0: 0      (32 x 260 = 8320)     H1: 8320
//   C0: 16640                        C1: 24960
//   WTraw0: 33280 (1024 x 8 = 8192)  WTraw1: 41472 (8192)
//   XWV: 49664 (1024)  B1P: 50688 (1024)  XR: 51712 (64)
//   total 51776 floats = 207104 bytes
// =============================================================================
#define HS    260
#define SMEM_FLOATS 51776
#define SMEM_BYTES  (SMEM_FLOATS*4)

__global__ __launch_bounds__(256)
void k_lstm(const float* __restrict__ x, const float* __restrict__ particles,
            const float* __restrict__ q, const float* __restrict__ e,
            const float* __restrict__ Wih0, const float* __restrict__ Whh0,
            const float* __restrict__ b0,
            const float* __restrict__ Wih1, const float* __restrict__ Whh1,
            const float* __restrict__ b1,
            const float* __restrict__ eps_h, const float* __restrict__ eps_c,
            float* __restrict__ pf){
    extern __shared__ __align__(16) float sm[];
    float* H0   = sm;
    float* H1   = sm + 8320;
    float* C0   = sm + 16640;
    float* C1   = sm + 24960;
    float* WT0  = sm + 33280;
    float* WT1  = sm + 41472;
    float* XWV  = sm + 49664;
    float* B1P  = sm + 50688;
    float* XR   = sm + 51712;

    int tid  = threadIdx.x;
    int lane = tid & 31;
    int warp = tid >> 5;            // 0..7, owns N-tiles warp*16..warp*16+15
    int r = lane >> 2;              // fragment row 0..7
    int c = lane & 3;               // fragment col 0..3
    int blk = blockIdx.x;
    int b  = blk >> 3;
    int p0 = (blk & 7) * 32;

    // per-thread staging map: 8 chunks, chunk i -> row jp, half
    // ch = i*256 + tid ; jp = ch>>1 ; half = ch&1 ; jo = ((jp&3)<<8)|(jp>>2)
    uint32_t wt_base[2];
    wt_base[0] = (uint32_t)__cvta_generic_to_shared(WT0);
    wt_base[1] = (uint32_t)__cvta_generic_to_shared(WT1);

    // ---- init: load particle states (stride-260 layout) ----
    for (int idx = tid; idx < 8192; idx += 256){
        int row = idx >> 8, u = idx & 255; int p = p0 + row;
        size_t base0 = ((size_t)(0*BSC + b)*NHC + u)*NPARTC;
        size_t base1 = ((size_t)(1*BSC + b)*NHC + u)*NPARTC;
        H0[row*HS + u] = particles[base0 + p];
        H1[row*HS + u] = particles[base1 + p];
        C0[row*HS + u] = particles[base0 + MIDP + p];
        C1[row*HS + u] = particles[base1 + MIDP + p];
    }
    for (int jp = tid; jp < 1024; jp += 256){
        int jo = ((jp & 3) << 8) | (jp >> 2);
        B1P[jp] = b1[jo];
    }
    __syncthreads();

    // ---- time loop ----
    for (int t = 0; t < TTC; t++){
        if (tid < 64) XR[tid] = x[(b*TTC + t)*DINC + tid];
        __syncthreads();
        // input projection (permuted j' = 4u+gate), float4-vectorized
        for (int jp = tid; jp < 1024; jp += 256){
            int jo = ((jp & 3) << 8) | (jp >> 2);
            const float4* wr = reinterpret_cast<const float4*>(Wih0 + jo*DINC);
            const float4* xr = reinterpret_cast<const float4*>(XR);
            float acc = b0[jo];
            #pragma unroll
            for (int k4 = 0; k4 < DINC/4; k4++){
                float4 wv = wr[k4]; float4 xv = xr[k4];
                acc = fmaf(xv.x, wv.x, acc);
                acc = fmaf(xv.y, wv.y, acc);
                acc = fmaf(xv.z, wv.z, acc);
                acc = fmaf(xv.w, wv.w, acc);
            }
            XWV[jp] = acc;
        }
        // XWV visibility covered by mainloop barriers below

        for (int layer = 0; layer < 2; layer++){
            const float* Wlo_m = (layer==0) ? Whh0 : Wih1;   // k < 256
            const float* Whi_m = Whh1;                        // k >= 256 (layer1)
            float* Hs = (layer==0) ? H0 : H1;
            float* Cs = (layer==0) ? C0 : C1;
            const float* pre = (layer==0) ? XWV : B1P;
            int nkt = (layer==0) ? 32 : 64;                   // 8-k tiles

            float4 d4[2][16];
            #pragma unroll
            for (int ms=0; ms<2; ms++)
                #pragma unroll
                for (int j=0; j<16; j++) d4[ms][j] = make_float4(0.f,0.f,0.f,0.f);

            // ---- stage tile 0 into buf 0 ----
            {
                const float* Ws = Wlo_m;        // tile 0 always k<256
                #pragma unroll
                for (int i=0;i<8;i++){
                    int ch = i*256 + tid;
                    int jp = ch >> 1;
                    int half = ch & 1;
                    int jo = ((jp & 3) << 8) | (jp >> 2);
                    int dstk = (half*4) ^ ((jp & 1) << 2);
                    cp16(wt_base[0] + (uint32_t)(jp*8 + dstk)*4,
                         Ws + (size_t)jo*256 + half*4);
                }
                asm volatile("cp.async.commit_group;");
            }

            for (int kt = 0; kt < nkt; kt++){
                int pb = kt & 1;
                bool havenext = (kt+1 < nkt);
                if (havenext){
                    const float* Ws = (kt+1 < 32) ? Wlo_m : Whi_m;
                    int k0 = ((kt+1) & 31) * 8;
                    #pragma unroll
                    for (int i=0;i<8;i++){
                        int ch = i*256 + tid;
                        int jp = ch >> 1;
                        int half = ch & 1;
                        int jo = ((jp & 3) << 8) | (jp >> 2);
                        int dstk = (half*4) ^ ((jp & 1) << 2);
                        cp16(wt_base[pb^1] + (uint32_t)(jp*8 + dstk)*4,
                             Ws + (size_t)jo*256 + k0 + half*4);
                    }
                    asm volatile("cp.async.commit_group;");
                    asm volatile("cp.async.wait_group 1;");
                } else {
                    asm volatile("cp.async.wait_group 0;");
                }
                __syncthreads();   // tile kt data visible to all

                // ---- A fragments (hi/lo) from smem H
                const float* Asrc; int kloc;
                if (layer==0){ Asrc = H0; kloc = kt*8; }
                else if (kt < 32){ Asrc = H0; kloc = kt*8; }
                else { Asrc = H1; kloc = (kt-32)*8; }
                uint32_t ahi[2][4], alo[2][4];
                #pragma unroll
                for (int ms=0; ms<2; ms++){
                    #pragma unroll
                    for (int ii=0; ii<4; ii++){
                        int row = ms*16 + r + ((ii & 1) << 3);
                        int col = kloc + c + ((ii >> 1) << 2);
                        float av = Asrc[row*HS + col];
                        uint32_t hb = f2tf(av);
                        ahi[ms][ii] = hb;
                        alo[ms][ii] = f2tf(av - __uint_as_float(hb));
                    }
                }
                // ---- mma over owned N-tiles (consumer-side hi/lo conversion)
                const float* W = pb ? WT1 : WT0;
                #pragma unroll
                for (int j=0; j<16; j++){
                    int np = (warp*16 + j)*8 + r;
                    int xr2 = (np & 1) << 2;
                    float braw0 = W[np*8 + (c ^ xr2)];
                    float braw1 = W[np*8 + ((c+4) ^ xr2)];
                    uint32_t bh0 = f2tf(braw0);
                    uint32_t bl0 = f2tf(braw0 - __uint_as_float(bh0));
                    uint32_t bh1 = f2tf(braw1);
                    uint32_t bl1 = f2tf(braw1 - __uint_as_float(bh1));
                    #pragma unroll
                    for (int ms=0; ms<2; ms++){
                        mma_tf32(d4[ms][j], ahi[ms][0],ahi[ms][1],ahi[ms][2],ahi[ms][3], bh0, bh1);
                        mma_tf32(d4[ms][j], ahi[ms][0],ahi[ms][1],ahi[ms][2],ahi[ms][3], bl0, bl1);
                        mma_tf32(d4[ms][j], alo[ms][0],alo[ms][1],alo[ms][2],alo[ms][3], bh0, bh1);
                    }
                }
                __syncthreads();   // reads of buf pb done before next overwrite
            }

            // ---- epilogue: add pre-activation, reunite gate quads, cell update
            #pragma unroll
            for (int ms=0; ms<2; ms++){
                #pragma unroll
                for (int j=0; j<16; j++){
                    int nt = warp*16 + j;
                    int jp0 = nt*8 + 2*c;
                    float pz0 = pre[jp0], pz1 = pre[jp0+1];
                    float g0 = d4[ms][j].x + pz0;
                    float g1 = d4[ms][j].y + pz1;
                    float g2 = d4[ms][j].z + pz0;
                    float g3 = d4[ms][j].w + pz1;
                    float e0 = __shfl_xor_sync(0xFFFFFFFFu, g0, 1);
                    float e1 = __shfl_xor_sync(0xFFFFFFFFu, g1, 1);
                    float e2 = __shfl_xor_sync(0xFFFFFFFFu, g2, 1);
                    float e3 = __shfl_xor_sync(0xFFFFFFFFu, g3, 1);
                    if (!(lane & 1)){
                        int u = nt*2 + (c >> 1);
                        int row0 = ms*16 + r;
                        {
                            float cold = Cs[row0*HS + u];
                            float cn = sigf(g1)*cold + sigf(g0)*tanhfa(e0);
                            float hn = sigf(e1)*tanhfa(cn);
                            Cs[row0*HS + u] = cn;
                            Hs[row0*HS + u] = hn;
                        }
                        {
                            float cold = Cs[(row0+8)*HS + u];
                            float cn = sigf(g3)*cold + sigf(g2)*tanhfa(e2);
                            float hn = sigf(e3)*tanhfa(cn);
                            Cs[(row0+8)*HS + u] = cn;
                            Hs[(row0+8)*HS + u] = hn;
                        }
                    }
                }
            }
            __syncthreads();   // H updated before next layer / next t reads
        }
    }

    // ---- write pr = final state + noise into pf (l,b,u,512) ----
    float sq = sqrtf(q[0]*q[0]);
    float se = sqrtf(e[0]*e[0]);
    for (int idx = tid; idx < 8192; idx += 256){
        int row = idx >> 8, u = idx & 255; int p = p0 + row;
        size_t o0 = ((size_t)(0*BSC + b)*NHC + u)*NPARTC;
        size_t o1 = ((size_t)(1*BSC + b)*NHC + u)*NPARTC;
        int e0i = ((p*LSC + 0)*BSC + b)*NHC + u;
        int e1i = ((p*LSC + 1)*BSC + b)*NHC + u;
        pf[o0 + p]        = H0[row*HS+u] + sq*eps_h[e0i];
        pf[o1 + p]        = H1[row*HS+u] + sq*eps_h[e1i];
        pf[o0 + MIDP + p] = C0[row*HS+u] + se*eps_c[e0i];
        pf[o1 + MIDP + p] = C1[row*HS+u] + se*eps_c[e1i];
    }
}

// ---------------- obs + weight update; preW staged into out.wf ---------------
__global__ __launch_bounds__(512)
void k_stats1(const float* __restrict__ weights, const float* __restrict__ y,
              const float* __restrict__ r, const float* __restrict__ pf,
              const float* __restrict__ Wh, const float* __restrict__ bh,
              float* __restrict__ out){
    __shared__ __align__(16) float ws[NHC];
    __shared__ float red[512];
    int b = blockIdx.x; int tid = threadIdx.x;
    if (tid < NHC) ws[tid] = Wh[tid];
    __syncthreads();
    float Yv = bh[0];
    const float* base = pf + ((size_t)(BSC + b)*NHC)*NPARTC;   // l=1
    for (int u=0; u<NHC; u++) Yv = fmaf(ws[u], base[(size_t)u*NPARTC + tid], Yv);
    float w  = logf(weights[b*NPARTC + tid]);
    float wsum = bsum(red, tid, 512, w);
    float s1   = bsum(red, tid, 512, Yv*w);
    float Wmu  = s1 / wsum;
    float cen  = Yv - Wmu;
    float cov  = bsum(red, tid, 512, cen*cen) / (float)(NPARTC-1) + r[0]*r[0];
    float s    = cov + 1e-6f;
    float innov = y[b] - Yv*w/wsum;
    out[OFF_WF + b*NPARTC + tid] = w - 0.5f*logf(s) - 0.5f*innov*innov/s;   // preW
}

// ---- normalize preW across the BATCH axis (reference quirk), in place -------
__global__ __launch_bounds__(512)
void k_norm(float* __restrict__ out){
    int n = threadIdx.x;
    float v[BSC];
    float s = 0.0f;
    #pragma unroll
    for (int b=0;b<BSC;b++){ v[b] = out[OFF_WF + b*NPARTC + n]; s += expf(v[b]); }
    float ls = logf(s);
    #pragma unroll
    for (int b=0;b<BSC;b++) out[OFF_WF + b*NPARTC + n] = expf(v[b] - ls);   // neww
}

// ---------------- per-(batch,half) resample: bitonic argsort of 256 ----------
__global__ __launch_bounds__(256)
void k_resample(const float* __restrict__ gumbel, float* __restrict__ out){
    __shared__ __align__(16) float key[256];
    __shared__ __align__(16) int   idxs[256];
    __shared__ __align__(16) float red[256];
    int blk = blockIdx.x; int b = blk>>1; int half = blk&1; int tid = threadIdx.x;
    float wh = out[OFF_WF + b*NPARTC + half*MIDP + tid];
    float ss = bsum(red, tid, 256, wh*wh);
    int dof = (1.0f/ss < (float)NPARTC/4.0f) ? 1 : 0;
    float soft = 0.5f*wh + 0.5f/(float)MIDP;
    key[tid]  = -(logf(soft) + gumbel[(b*2 + half)*MIDP + tid]);
    idxs[tid] = tid;
    __syncthreads();
    for (int k=2;k<=256;k<<=1){
        for (int j=k>>1;j>0;j>>=1){
            int ixj = tid ^ j;
            if (ixj > tid){
                bool up = ((tid & k) == 0);
                float a = key[tid], bk = key[ixj];
                if ((a > bk) == up){
                    key[tid]=bk; key[ixj]=a;
                    int t0=idxs[tid]; idxs[tid]=idxs[ixj]; idxs[ixj]=t0;
                }
            }
            __syncthreads();
        }
    }
    g_idx[blk*MIDP + tid] = idxs[tid];
    float lw = logf(wh/soft);
    float mx = bmax(red, tid, 256, lw);
    float se = bsum(red, tid, 256, expf(lw-mx));
    float lse = mx + logf(se);
    float wr = expf(lw - lse);
    out[OFF_WF + b*NPARTC + half*MIDP + tid] = dof ? wr : wh;
    if (tid==0) g_do[blk] = dof;
}

// ---------------- in-place gather on pf (per (b,half) permutation) -----------
__global__ __launch_bounds__(256)
void k_gather(float* __restrict__ pf){
    __shared__ __align__(16) float seg[8][256];
    __shared__ int idx_s[256];
    int blk = blockIdx.x;            // b*2+half
    int chunk = blockIdx.y;          // 0..63 -> 8 (l,u) rows each
    int b = blk>>1; int half = blk&1; int tid = threadIdx.x;
    if (!g_do[blk]) return;
    idx_s[tid] = g_idx[blk*MIDP + tid];
    int row0 = chunk*8;
    #pragma unroll
    for (int i=0;i<8;i++){
        int rr = row0 + i;
        int l = rr >> 8, u = rr & 255;
        seg[i][tid] = pf[(((size_t)(l*BSC+b))*NHC + u)*NPARTC + half*MIDP + tid];
    }
    __syncthreads();
    #pragma unroll
    for (int i=0;i<8;i++){
        int rr = row0 + i;
        int l = rr >> 8, u = rr & 255;
        pf[(((size_t)(l*BSC+b))*NHC + u)*NPARTC + half*MIDP + tid] = seg[i][idx_s[tid]];
    }
}

// ---------------- final estimate (obs fused, 16 blocks) ----------------------
__global__ __launch_bounds__(512)
void k_stats2(const float* __restrict__ y, const float* __restrict__ r,
              const float* __restrict__ pf, const float* __restrict__ Wh,
              const float* __restrict__ bh, float* __restrict__ out){
    __shared__ __align__(16) float ws[NHC];
    __shared__ float red[512];
    int b = blockIdx.x; int tid = threadIdx.x;
    if (tid < NHC) ws[tid] = Wh[tid];
    __syncthreads();
    float Yv = bh[0];
    const float* base = pf + ((size_t)(BSC + b)*NHC)*NPARTC;   // l=1
    for (int u=0; u<NHC; u++) Yv = fmaf(ws[u], base[(size_t)u*NPARTC + tid], Yv);
    float wv = out[OFF_WF + b*NPARTC + tid];
    float wsum = bsum(red, tid, 512, wv);
    float Wmu  = bsum(red, tid, 512, Yv*wv) / wsum;
    float cen  = Yv - Wmu;
    float cov  = bsum(red, tid, 512, cen*cen) / (float)(NPARTC-1) + r[0]*r[0];
    if (tid==0){
        out[OFF_WMU + b] = Wmu;
        out[OFF_SIG + b] = cov;
    }
}

// ---- scalars recomputed from already-written W_mu/sig -----------------------
__global__ __launch_bounds__(32)
void k_scalars(const float* __restrict__ y, float* __restrict__ out){
    if (threadIdx.x != 0) return;
    float l = 0.0f, nq = 0.0f;
    for (int b=0;b<BSC;b++){
        float s = out[OFF_SIG + b] + 1e-6f;
        float inn = y[b] - out[OFF_WMU + b];
        float qf = inn*inn/s;
        l += -0.5f*logf(s) - 0.5f*qf;
        nq += qf;
    }
    out[OFF_L]   = l;
    out[OFF_NIS] = nq / (float)BSC;
}

// =============================================================================
extern "C" void kernel_launch(void* const* d_in, const int* in_sizes, int n_in,
                              void* d_out, int out_size){
    const float* x        = (const float*)d_in[0];
    const float* y        = (const float*)d_in[1];
    const float* particles= (const float*)d_in[2];
    const float* weights  = (const float*)d_in[3];
    const float* q        = (const float*)d_in[4];
    const float* e        = (const float*)d_in[5];
    const float* r        = (const float*)d_in[6];
    const float* Wih0     = (const float*)d_in[7];
    const float* Whh0     = (const float*)d_in[8];
    const float* b0       = (const float*)d_in[9];
    const float* Wih1     = (const float*)d_in[10];
    const float* Whh1     = (const float*)d_in[11];
    const float* b1       = (const float*)d_in[12];
    const float* Wh       = (const float*)d_in[13];
    const float* bh       = (const float*)d_in[14];
    const float* eps_h    = (const float*)d_in[15];
    const float* eps_c    = (const float*)d_in[16];
    const float* gumbel   = (const float*)d_in[17];
    float* out = (float*)d_out;
    float* pf  = out + OFF_PF;

    static bool attr_set = false;
    if (!attr_set){
        cudaFuncSetAttribute(k_lstm, cudaFuncAttributeMaxDynamicSharedMemorySize, SMEM_BYTES);
        attr_set = true;
    }

    // 1. full recurrence (tensor-core 3xTF32 + cp.async staging); writes pr into pf
    k_lstm<<<128, 256, SMEM_BYTES>>>(x, particles, q, e,
                                     Wih0, Whh0, b0, Wih1, Whh1, b1,
                                     eps_h, eps_c, pf);
    // 2. obs + weight update (preW -> out.wf), batch-axis norm in place
    k_stats1<<<BSC, 512>>>(weights, y, r, pf, Wh, bh, out);
    k_norm<<<1, 512>>>(out);
    // 3. resample halves (reads neww from out.wf, writes final wf + g_idx/g_do)
    k_resample<<<BSC*2, 256>>>(gumbel, out);
    // 4. in-place gather pr -> pf
    k_gather<<<dim3(BSC*2, 64), 256>>>(pf);
    // 5. final obs + estimate, then scalars
    k_stats2<<<BSC, 512>>>(y, r, pf, Wh, bh, out);
    k_scalars<<<1, 32>>>(y, out);
}

// round 16
// speedup vs baseline: 1.3891x; 1.1072x over previous
#include <cuda_runtime.h>
#include <math.h>
#include <stdint.h>

// Problem constants
#define LSC   2
#define BSC   16
#define NHC   256
#define NPARTC 512
#define MIDP  256
#define TTC   16
#define DINC  64
#define FHC   1024

// Output layout: tuple (W_mu(16,1), sig(16,1,1), pf(2,16,256,512), wf(16,512), l, nis)
#define OFF_WMU 0
#define OFF_SIG 16
#define OFF_PF  32
#define OFF_WF  (32 + LSC*BSC*NHC*NPARTC)
#define OFF_L   (OFF_WF + BSC*NPARTC)
#define OFF_NIS (OFF_L + 1)

// ---- tiny globals only (33 KB, proven-safe config) --------------------------
__device__ int g_idx[BSC*2*MIDP];
__device__ int g_do[BSC*2];

__device__ __forceinline__ float sigf(float x)   { return 1.0f/(1.0f+__expf(-x)); }
__device__ __forceinline__ float tanhfa(float x) { return 2.0f/(1.0f+__expf(-2.0f*x)) - 1.0f; }

// split (a0,a1) into packed bf16x2 hi and lo (lo = bf16(a - hi)); a0 in low half
__device__ __forceinline__ void bfsplit2(float a0, float a1, uint32_t& hi, uint32_t& lo){
    uint32_t h;
    asm("cvt.rn.bf16x2.f32 %0, %1, %2;" : "=r"(h) : "f"(a1), "f"(a0));
    float h0 = __uint_as_float(h << 16);
    float h1 = __uint_as_float(h & 0xFFFF0000u);
    float l0 = a0 - h0, l1 = a1 - h1;
    uint32_t l;
    asm("cvt.rn.bf16x2.f32 %0, %1, %2;" : "=r"(l) : "f"(l1), "f"(l0));
    hi = h; lo = l;
}
__device__ __forceinline__ void mma_bf16(float4& d, uint32_t a0, uint32_t a1, uint32_t b0){
    asm volatile("mma.sync.aligned.m16n8k8.row.col.f32.bf16.bf16.f32 "
        "{%0,%1,%2,%3}, {%4,%5}, {%6}, {%0,%1,%2,%3};"
        : "+f"(d.x), "+f"(d.y), "+f"(d.z), "+f"(d.w)
        : "r"(a0), "r"(a1), "r"(b0));
}
__device__ __forceinline__ void cp16(uint32_t dst, const void* src){
    asm volatile("cp.async.ca.shared.global [%0], [%1], 16;" :: "r"(dst), "l"(src));
}

__device__ __forceinline__ float bsum(float* red, int tid, int nthr, float v){
    red[tid]=v; __syncthreads();
    for (int s=nthr>>1; s>0; s>>=1){ if(tid<s) red[tid]+=red[tid+s]; __syncthreads(); }
    float r = red[0]; __syncthreads(); return r;
}
__device__ __forceinline__ float bmax(float* red, int tid, int nthr, float v){
    red[tid]=v; __syncthreads();
    for (int s=nthr>>1; s>0; s>>=1){ if(tid<s) red[tid]=fmaxf(red[tid],red[tid+s]); __syncthreads(); }
    float r = red[0]; __syncthreads(); return r;
}

// =============================================================================
// Persistent LSTM kernel, tensor-core (3x bf16 hi/lo) mainloop, cp.async staging.
// 128 CTAs x 256 threads. CTA = (batch b, particles p0..p0+31).
// Gates G[32][1024] = H[32][K] @ W^T via mma.sync m16n8k8 bf16, 3-term split.
// Weight tiles [1024 j' x 8k] staged RAW with cp.async (pair-coalesced,
// XOR-swizzled), double buffered. Conversion on the consumer side.
// smem floats:
//   H0: 0      (32 x 260 = 8320)     H1: 8320
//   C0: 16640                        C1: 24960
//   WTraw0: 33280 (1024 x 8 = 8192)  WTraw1: 41472 (8192)
//   XWV: 49664 (1024)  B1P: 50688 (1024)  XR: 51712 (64)
//   total 51776 floats = 207104 bytes
// =============================================================================
#define HS    260
#define SMEM_FLOATS 51776
#define SMEM_BYTES  (SMEM_FLOATS*4)

__global__ __launch_bounds__(256)
void k_lstm(const float* __restrict__ x, const float* __restrict__ particles,
            const float* __restrict__ q, const float* __restrict__ e,
            const float* __restrict__ Wih0, const float* __restrict__ Whh0,
            const float* __restrict__ b0,
            const float* __restrict__ Wih1, const float* __restrict__ Whh1,
            const float* __restrict__ b1,
            const float* __restrict__ eps_h, const float* __restrict__ eps_c,
            float* __restrict__ pf){
    extern __shared__ __align__(16) float sm[];
    float* H0   = sm;
    float* H1   = sm + 8320;
    float* C0   = sm + 16640;
    float* C1   = sm + 24960;
    float* WT0  = sm + 33280;
    float* WT1  = sm + 41472;
    float* XWV  = sm + 49664;
    float* B1P  = sm + 50688;
    float* XR   = sm + 51712;

    int tid  = threadIdx.x;
    int lane = tid & 31;
    int warp = tid >> 5;            // 0..7, owns N-tiles warp*16..warp*16+15
    int r = lane >> 2;              // fragment row 0..7
    int c = lane & 3;               // fragment col 0..3
    int blk = blockIdx.x;
    int b  = blk >> 3;
    int p0 = (blk & 7) * 32;

    uint32_t wt_base[2];
    wt_base[0] = (uint32_t)__cvta_generic_to_shared(WT0);
    wt_base[1] = (uint32_t)__cvta_generic_to_shared(WT1);

    // ---- init: load particle states (stride-260 layout) ----
    for (int idx = tid; idx < 8192; idx += 256){
        int row = idx >> 8, u = idx & 255; int p = p0 + row;
        size_t base0 = ((size_t)(0*BSC + b)*NHC + u)*NPARTC;
        size_t base1 = ((size_t)(1*BSC + b)*NHC + u)*NPARTC;
        H0[row*HS + u] = particles[base0 + p];
        H1[row*HS + u] = particles[base1 + p];
        C0[row*HS + u] = particles[base0 + MIDP + p];
        C1[row*HS + u] = particles[base1 + MIDP + p];
    }
    for (int jp = tid; jp < 1024; jp += 256){
        int jo = ((jp & 3) << 8) | (jp >> 2);
        B1P[jp] = b1[jo];
    }
    __syncthreads();

    // ---- time loop ----
    for (int t = 0; t < TTC; t++){
        if (tid < 64) XR[tid] = x[(b*TTC + t)*DINC + tid];
        __syncthreads();
        // input projection (permuted j' = 4u+gate), float4-vectorized
        for (int jp = tid; jp < 1024; jp += 256){
            int jo = ((jp & 3) << 8) | (jp >> 2);
            const float4* wr = reinterpret_cast<const float4*>(Wih0 + jo*DINC);
            const float4* xr = reinterpret_cast<const float4*>(XR);
            float acc = b0[jo];
            #pragma unroll
            for (int k4 = 0; k4 < DINC/4; k4++){
                float4 wv = wr[k4]; float4 xv = xr[k4];
                acc = fmaf(xv.x, wv.x, acc);
                acc = fmaf(xv.y, wv.y, acc);
                acc = fmaf(xv.z, wv.z, acc);
                acc = fmaf(xv.w, wv.w, acc);
            }
            XWV[jp] = acc;
        }
        // XWV visibility covered by mainloop barriers below

        for (int layer = 0; layer < 2; layer++){
            const float* Wlo_m = (layer==0) ? Whh0 : Wih1;   // k < 256
            const float* Whi_m = Whh1;                        // k >= 256 (layer1)
            float* Hs = (layer==0) ? H0 : H1;
            float* Cs = (layer==0) ? C0 : C1;
            const float* pre = (layer==0) ? XWV : B1P;
            int nkt = (layer==0) ? 32 : 64;                   // 8-k tiles

            float4 d4[2][16];
            #pragma unroll
            for (int ms=0; ms<2; ms++)
                #pragma unroll
                for (int j=0; j<16; j++) d4[ms][j] = make_float4(0.f,0.f,0.f,0.f);

            // ---- stage tile 0 into buf 0 ----
            {
                const float* Ws = Wlo_m;        // tile 0 always k<256
                #pragma unroll
                for (int i=0;i<8;i++){
                    int ch = i*256 + tid;
                    int jp = ch >> 1;
                    int half = ch & 1;
                    int jo = ((jp & 3) << 8) | (jp >> 2);
                    int dstk = (half*4) ^ ((jp & 1) << 2);
                    cp16(wt_base[0] + (uint32_t)(jp*8 + dstk)*4,
                         Ws + (size_t)jo*256 + half*4);
                }
                asm volatile("cp.async.commit_group;");
            }

            for (int kt = 0; kt < nkt; kt++){
                int pb = kt & 1;
                bool havenext = (kt+1 < nkt);
                if (havenext){
                    const float* Ws = (kt+1 < 32) ? Wlo_m : Whi_m;
                    int k0 = ((kt+1) & 31) * 8;
                    #pragma unroll
                    for (int i=0;i<8;i++){
                        int ch = i*256 + tid;
                        int jp = ch >> 1;
                        int half = ch & 1;
                        int jo = ((jp & 3) << 8) | (jp >> 2);
                        int dstk = (half*4) ^ ((jp & 1) << 2);
                        cp16(wt_base[pb^1] + (uint32_t)(jp*8 + dstk)*4,
                             Ws + (size_t)jo*256 + k0 + half*4);
                    }
                    asm volatile("cp.async.commit_group;");
                    asm volatile("cp.async.wait_group 1;");
                } else {
                    asm volatile("cp.async.wait_group 0;");
                }
                __syncthreads();   // tile kt data visible to all

                // ---- A fragments (bf16 hi/lo packed) from smem H
                const float* Asrc; int kloc;
                if (layer==0){ Asrc = H0; kloc = kt*8; }
                else if (kt < 32){ Asrc = H0; kloc = kt*8; }
                else { Asrc = H1; kloc = (kt-32)*8; }
                uint32_t a0hi[2], a0lo[2], a1hi[2], a1lo[2];
                #pragma unroll
                for (int ms=0; ms<2; ms++){
                    int row0 = ms*16 + r;
                    float2 av0 = *reinterpret_cast<const float2*>(&Asrc[row0*HS + kloc + 2*c]);
                    float2 av1 = *reinterpret_cast<const float2*>(&Asrc[(row0+8)*HS + kloc + 2*c]);
                    bfsplit2(av0.x, av0.y, a0hi[ms], a0lo[ms]);
                    bfsplit2(av1.x, av1.y, a1hi[ms], a1lo[ms]);
                }
                // ---- mma over owned N-tiles (consumer-side hi/lo conversion)
                const float* W = pb ? WT1 : WT0;
                #pragma unroll
                for (int j=0; j<16; j++){
                    int np = (warp*16 + j)*8 + r;
                    int xr2 = (np & 1) << 2;
                    float2 bw = *reinterpret_cast<const float2*>(&W[np*8 + ((2*c) ^ xr2)]);
                    uint32_t bhi, blo;
                    bfsplit2(bw.x, bw.y, bhi, blo);
                    #pragma unroll
                    for (int ms=0; ms<2; ms++){
                        mma_bf16(d4[ms][j], a0hi[ms], a1hi[ms], bhi);
                        mma_bf16(d4[ms][j], a0hi[ms], a1hi[ms], blo);
                        mma_bf16(d4[ms][j], a0lo[ms], a1lo[ms], bhi);
                    }
                }
                __syncthreads();   // reads of buf pb done before next overwrite
            }

            // ---- epilogue: add pre-activation, reunite gate quads, cell update
            #pragma unroll
            for (int ms=0; ms<2; ms++){
                #pragma unroll
                for (int j=0; j<16; j++){
                    int nt = warp*16 + j;
                    int jp0 = nt*8 + 2*c;
                    float pz0 = pre[jp0], pz1 = pre[jp0+1];
                    float g0 = d4[ms][j].x + pz0;
                    float g1 = d4[ms][j].y + pz1;
                    float g2 = d4[ms][j].z + pz0;
                    float g3 = d4[ms][j].w + pz1;
                    float e0 = __shfl_xor_sync(0xFFFFFFFFu, g0, 1);
                    float e1 = __shfl_xor_sync(0xFFFFFFFFu, g1, 1);
                    float e2 = __shfl_xor_sync(0xFFFFFFFFu, g2, 1);
                    float e3 = __shfl_xor_sync(0xFFFFFFFFu, g3, 1);
                    if (!(lane & 1)){
                        int u = nt*2 + (c >> 1);
                        int row0 = ms*16 + r;
                        {
                            float cold = Cs[row0*HS + u];
                            float cn = sigf(g1)*cold + sigf(g0)*tanhfa(e0);
                            float hn = sigf(e1)*tanhfa(cn);
                            Cs[row0*HS + u] = cn;
                            Hs[row0*HS + u] = hn;
                        }
                        {
                            float cold = Cs[(row0+8)*HS + u];
                            float cn = sigf(g3)*cold + sigf(g2)*tanhfa(e2);
                            float hn = sigf(e3)*tanhfa(cn);
                            Cs[(row0+8)*HS + u] = cn;
                            Hs[(row0+8)*HS + u] = hn;
                        }
                    }
                }
            }
            __syncthreads();   // H updated before next layer / next t reads
        }
    }

    // ---- write pr = final state + noise into pf (l,b,u,512) ----
    float sq = sqrtf(q[0]*q[0]);
    float se = sqrtf(e[0]*e[0]);
    for (int idx = tid; idx < 8192; idx += 256){
        int row = idx >> 8, u = idx & 255; int p = p0 + row;
        size_t o0 = ((size_t)(0*BSC + b)*NHC + u)*NPARTC;
        size_t o1 = ((size_t)(1*BSC + b)*NHC + u)*NPARTC;
        int e0i = ((p*LSC + 0)*BSC + b)*NHC + u;
        int e1i = ((p*LSC + 1)*BSC + b)*NHC + u;
        pf[o0 + p]        = H0[row*HS+u] + sq*eps_h[e0i];
        pf[o1 + p]        = H1[row*HS+u] + sq*eps_h[e1i];
        pf[o0 + MIDP + p] = C0[row*HS+u] + se*eps_c[e0i];
        pf[o1 + MIDP + p] = C1[row*HS+u] + se*eps_c[e1i];
    }
}

// ---------------- obs + weight update; preW staged into out.wf ---------------
__global__ __launch_bounds__(512)
void k_stats1(const float* __restrict__ weights, const float* __restrict__ y,
              const float* __restrict__ r, const float* __restrict__ pf,
              const float* __restrict__ Wh, const float* __restrict__ bh,
              float* __restrict__ out){
    __shared__ __align__(16) float ws[NHC];
    __shared__ float red[512];
    int b = blockIdx.x; int tid = threadIdx.x;
    if (tid < NHC) ws[tid] = Wh[tid];
    __syncthreads();
    float Yv = bh[0];
    const float* base = pf + ((size_t)(BSC + b)*NHC)*NPARTC;   // l=1
    for (int u=0; u<NHC; u++) Yv = fmaf(ws[u], base[(size_t)u*NPARTC + tid], Yv);
    float w  = logf(weights[b*NPARTC + tid]);
    float wsum = bsum(red, tid, 512, w);
    float s1   = bsum(red, tid, 512, Yv*w);
    float Wmu  = s1 / wsum;
    float cen  = Yv - Wmu;
    float cov  = bsum(red, tid, 512, cen*cen) / (float)(NPARTC-1) + r[0]*r[0];
    float s    = cov + 1e-6f;
    float innov = y[b] - Yv*w/wsum;
    out[OFF_WF + b*NPARTC + tid] = w - 0.5f*logf(s) - 0.5f*innov*innov/s;   // preW
}

// ---- normalize preW across the BATCH axis (reference quirk), in place -------
__global__ __launch_bounds__(512)
void k_norm(float* __restrict__ out){
    int n = threadIdx.x;
    float v[BSC];
    float s = 0.0f;
    #pragma unroll
    for (int b=0;b<BSC;b++){ v[b] = out[OFF_WF + b*NPARTC + n]; s += expf(v[b]); }
    float ls = logf(s);
    #pragma unroll
    for (int b=0;b<BSC;b++) out[OFF_WF + b*NPARTC + n] = expf(v[b] - ls);   // neww
}

// ---------------- per-(batch,half) resample: bitonic argsort of 256 ----------
__global__ __launch_bounds__(256)
void k_resample(const float* __restrict__ gumbel, float* __restrict__ out){
    __shared__ __align__(16) float key[256];
    __shared__ __align__(16) int   idxs[256];
    __shared__ __align__(16) float red[256];
    int blk = blockIdx.x; int b = blk>>1; int half = blk&1; int tid = threadIdx.x;
    float wh = out[OFF_WF + b*NPARTC + half*MIDP + tid];
    float ss = bsum(red, tid, 256, wh*wh);
    int dof = (1.0f/ss < (float)NPARTC/4.0f) ? 1 : 0;
    float soft = 0.5f*wh + 0.5f/(float)MIDP;
    key[tid]  = -(logf(soft) + gumbel[(b*2 + half)*MIDP + tid]);
    idxs[tid] = tid;
    __syncthreads();
    for (int k=2;k<=256;k<<=1){
        for (int j=k>>1;j>0;j>>=1){
            int ixj = tid ^ j;
            if (ixj > tid){
                bool up = ((tid & k) == 0);
                float a = key[tid], bk = key[ixj];
                if ((a > bk) == up){
                    key[tid]=bk; key[ixj]=a;
                    int t0=idxs[tid]; idxs[tid]=idxs[ixj]; idxs[ixj]=t0;
                }
            }
            __syncthreads();
        }
    }
    g_idx[blk*MIDP + tid] = idxs[tid];
    float lw = logf(wh/soft);
    float mx = bmax(red, tid, 256, lw);
    float se = bsum(red, tid, 256, expf(lw-mx));
    float lse = mx + logf(se);
    float wr = expf(lw - lse);
    out[OFF_WF + b*NPARTC + half*MIDP + tid] = dof ? wr : wh;
    if (tid==0) g_do[blk] = dof;
}

// ---------------- in-place gather on pf (per (b,half) permutation) -----------
__global__ __launch_bounds__(256)
void k_gather(float* __restrict__ pf){
    __shared__ __align__(16) float seg[8][256];
    __shared__ int idx_s[256];
    int blk = blockIdx.x;            // b*2+half
    int chunk = blockIdx.y;          // 0..63 -> 8 (l,u) rows each
    int b = blk>>1; int half = blk&1; int tid = threadIdx.x;
    if (!g_do[blk]) return;
    idx_s[tid] = g_idx[blk*MIDP + tid];
    int row0 = chunk*8;
    #pragma unroll
    for (int i=0;i<8;i++){
        int rr = row0 + i;
        int l = rr >> 8, u = rr & 255;
        seg[i][tid] = pf[(((size_t)(l*BSC+b))*NHC + u)*NPARTC + half*MIDP + tid];
    }
    __syncthreads();
    #pragma unroll
    for (int i=0;i<8;i++){
        int rr = row0 + i;
        int l = rr >> 8, u = rr & 255;
        pf[(((size_t)(l*BSC+b))*NHC + u)*NPARTC + half*MIDP + tid] = seg[i][idx_s[tid]];
    }
}

// ---------------- final estimate (obs fused, 16 blocks) ----------------------
__global__ __launch_bounds__(512)
void k_stats2(const float* __restrict__ y, const float* __restrict__ r,
              const float* __restrict__ pf, const float* __restrict__ Wh,
              const float* __restrict__ bh, float* __restrict__ out){
    __shared__ __align__(16) float ws[NHC];
    __shared__ float red[512];
    int b = blockIdx.x; int tid = threadIdx.x;
    if (tid < NHC) ws[tid] = Wh[tid];
    __syncthreads();
    float Yv = bh[0];
    const float* base = pf + ((size_t)(BSC + b)*NHC)*NPARTC;   // l=1
    for (int u=0; u<NHC; u++) Yv = fmaf(ws[u], base[(size_t)u*NPARTC + tid], Yv);
    float wv = out[OFF_WF + b*NPARTC + tid];
    float wsum = bsum(red, tid, 512, wv);
    float Wmu  = bsum(red, tid, 512, Yv*wv) / wsum;
    float cen  = Yv - Wmu;
    float cov  = bsum(red, tid, 512, cen*cen) / (float)(NPARTC-1) + r[0]*r[0];
    if (tid==0){
        out[OFF_WMU + b] = Wmu;
        out[OFF_SIG + b] = cov;
    }
}

// ---- scalars recomputed from already-written W_mu/sig -----------------------
__global__ __launch_bounds__(32)
void k_scalars(const float* __restrict__ y, float* __restrict__ out){
    if (threadIdx.x != 0) return;
    float l = 0.0f, nq = 0.0f;
    for (int b=0;b<BSC;b++){
        float s = out[OFF_SIG + b] + 1e-6f;
        float inn = y[b] - out[OFF_WMU + b];
        float qf = inn*inn/s;
        l += -0.5f*logf(s) - 0.5f*qf;
        nq += qf;
    }
    out[OFF_L]   = l;
    out[OFF_NIS] = nq / (float)BSC;
}

// =============================================================================
extern "C" void kernel_launch(void* const* d_in, const int* in_sizes, int n_in,
                              void* d_out, int out_size){
    const float* x        = (const float*)d_in[0];
    const float* y        = (const float*)d_in[1];
    const float* particles= (const float*)d_in[2];
    const float* weights  = (const float*)d_in[3];
    const float* q        = (const float*)d_in[4];
    const float* e        = (const float*)d_in[5];
    const float* r        = (const float*)d_in[6];
    const float* Wih0     = (const float*)d_in[7];
    const float* Whh0     = (const float*)d_in[8];
    const float* b0       = (const float*)d_in[9];
    const float* Wih1     = (const float*)d_in[10];
    const float* Whh1     = (const float*)d_in[11];
    const float* b1       = (const float*)d_in[12];
    const float* Wh       = (const float*)d_in[13];
    const float* bh       = (const float*)d_in[14];
    const float* eps_h    = (const float*)d_in[15];
    const float* eps_c    = (const float*)d_in[16];
    const float* gumbel   = (const float*)d_in[17];
    float* out = (float*)d_out;
    float* pf  = out + OFF_PF;

    static bool attr_set = false;
    if (!attr_set){
        cudaFuncSetAttribute(k_lstm, cudaFuncAttributeMaxDynamicSharedMemorySize, SMEM_BYTES);
        attr_set = true;
    }

    // 1. full recurrence (tensor-core 3x bf16 + cp.async staging); writes pr into pf
    k_lstm<<<128, 256, SMEM_BYTES>>>(x, particles, q, e,
                                     Wih0, Whh0, b0, Wih1, Whh1, b1,
                                     eps_h, eps_c, pf);
    // 2. obs + weight update (preW -> out.wf), batch-axis norm in place
    k_stats1<<<BSC, 512>>>(weights, y, r, pf, Wh, bh, out);
    k_norm<<<1, 512>>>(out);
    // 3. resample halves (reads neww from out.wf, writes final wf + g_idx/g_do)
    k_resample<<<BSC*2, 256>>>(gumbel, out);
    // 4. in-place gather pr -> pf
    k_gather<<<dim3(BSC*2, 64), 256>>>(pf);
    // 5. final obs + estimate, then scalars
    k_stats2<<<BSC, 512>>>(y, r, pf, Wh, bh, out);
    k_scalars<<<1, 32>>>(y, out);
}

// round 17
// speedup vs baseline: 1.8636x; 1.3416x over previous
#include <cuda_runtime.h>
#include <math.h>
#include <stdint.h>

// Problem constants
#define LSC   2
#define BSC   16
#define NHC   256
#define NPARTC 512
#define MIDP  256
#define TTC   16
#define DINC  64
#define FHC   1024

// Output layout: tuple (W_mu(16,1), sig(16,1,1), pf(2,16,256,512), wf(16,512), l, nis)
#define OFF_WMU 0
#define OFF_SIG 16
#define OFF_PF  32
#define OFF_WF  (32 + LSC*BSC*NHC*NPARTC)
#define OFF_L   (OFF_WF + BSC*NPARTC)
#define OFF_NIS (OFF_L + 1)

// ---- tiny globals only (~33 KB, proven-safe config) -------------------------
__device__ int g_idx[BSC*2*MIDP];
__device__ int g_do[BSC*2];
__device__ unsigned int g_bar;      // monotonic ticket barrier (never reset)

__device__ __forceinline__ float sigf(float x)   { return 1.0f/(1.0f+__expf(-x)); }
__device__ __forceinline__ float tanhfa(float x) { return 2.0f/(1.0f+__expf(-2.0f*x)) - 1.0f; }

// split (a0,a1) into packed bf16x2 hi and lo (lo = bf16(a - hi)); a0 in low half
__device__ __forceinline__ void bfsplit2(float a0, float a1, uint32_t& hi, uint32_t& lo){
    uint32_t h;
    asm("cvt.rn.bf16x2.f32 %0, %1, %2;" : "=r"(h) : "f"(a1), "f"(a0));
    float h0 = __uint_as_float(h << 16);
    float h1 = __uint_as_float(h & 0xFFFF0000u);
    float l0 = a0 - h0, l1 = a1 - h1;
    uint32_t l;
    asm("cvt.rn.bf16x2.f32 %0, %1, %2;" : "=r"(l) : "f"(l1), "f"(l0));
    hi = h; lo = l;
}
__device__ __forceinline__ void mma_bf16(float4& d, uint32_t a0, uint32_t a1, uint32_t b0){
    asm volatile("mma.sync.aligned.m16n8k8.row.col.f32.bf16.bf16.f32 "
        "{%0,%1,%2,%3}, {%4,%5}, {%6}, {%0,%1,%2,%3};"
        : "+f"(d.x), "+f"(d.y), "+f"(d.z), "+f"(d.w)
        : "r"(a0), "r"(a1), "r"(b0));
}
__device__ __forceinline__ void cp16(uint32_t dst, const void* src){
    asm volatile("cp.async.ca.shared.global [%0], [%1], 16;" :: "r"(dst), "l"(src));
}

__device__ __forceinline__ float bsum(float* red, int tid, int nthr, float v){
    red[tid]=v; __syncthreads();
    for (int s=nthr>>1; s>0; s>>=1){ if(tid<s) red[tid]+=red[tid+s]; __syncthreads(); }
    float r = red[0]; __syncthreads(); return r;
}
__device__ __forceinline__ float bmax(float* red, int tid, int nthr, float v){
    red[tid]=v; __syncthreads();
    for (int s=nthr>>1; s>0; s>>=1){ if(tid<s) red[tid]=fmaxf(red[tid],red[tid+s]); __syncthreads(); }
    float r = red[0]; __syncthreads(); return r;
}

// =============================================================================
// k_prep: pre-split all recurrent weights into bf16 hi/lo tile images, parked
// in the pf region (scratch until pr is written). 96 tiles of 8192 uint32:
//   tile 0..31  : Whh0, k0 = tile*8        (layer0, kt)
//   tile 32..63 : Wih1, k0 = (tile-32)*8   (layer1, kt<32)
//   tile 64..95 : Whh1, k0 = (tile-64)*8   (layer1, kt>=32)
// Within a tile: hi[jp*4+cp] (4096), then lo[jp*4+cp] (4096);
//   packed pair = (W[jo][k0+2cp], W[jo][k0+2cp+1]), jo = ((jp&3)<<8)|(jp>>2)
// =============================================================================
__global__ __launch_bounds__(256)
void k_prep(const float* __restrict__ Whh0, const float* __restrict__ Wih1,
            const float* __restrict__ Whh1, uint32_t* __restrict__ scr){
    int tile = blockIdx.x;
    const float* Ws; int k0;
    if (tile < 32){ Ws = Whh0; k0 = tile*8; }
    else if (tile < 64){ Ws = Wih1; k0 = (tile-32)*8; }
    else { Ws = Whh1; k0 = (tile-64)*8; }
    uint32_t* hi = scr + (size_t)tile*8192;
    uint32_t* lo = hi + 4096;
    for (int idx = threadIdx.x; idx < 4096; idx += 256){
        int jp = idx >> 2, cp = idx & 3;
        int jo = ((jp & 3) << 8) | (jp >> 2);
        float w0 = Ws[jo*256 + k0 + cp*2];
        float w1 = Ws[jo*256 + k0 + cp*2 + 1];
        uint32_t h, l;
        bfsplit2(w0, w1, h, l);
        hi[idx] = h; lo[idx] = l;
    }
}

// =============================================================================
// Persistent LSTM kernel, tensor-core (3x bf16 hi/lo) mainloop.
// Weight tiles pre-split by k_prep; staging is fully coalesced cp.async.
// 128 CTAs x 256 threads; all-CTA ticket barrier before pr overwrites scratch.
// smem floats:
//   H0: 0 (8320)  H1: 8320  C0: 16640  C1: 24960
//   WT0: 33280 (8192 u32)   WT1: 41472 (8192 u32)
//   XWV: 49664 (1024)  B1P: 50688 (1024)  XR: 51712 (64)
//   total 51776 floats = 207104 bytes
// =============================================================================
#define HS    260
#define SMEM_FLOATS 51776
#define SMEM_BYTES  (SMEM_FLOATS*4)

__global__ __launch_bounds__(256)
void k_lstm(const float* __restrict__ x, const float* __restrict__ particles,
            const float* __restrict__ q, const float* __restrict__ e,
            const float* __restrict__ Wih0, const float* __restrict__ b0,
            const float* __restrict__ b1,
            const float* __restrict__ eps_h, const float* __restrict__ eps_c,
            const uint32_t* __restrict__ scr, float* __restrict__ pf){
    extern __shared__ __align__(16) float sm[];
    float* H0   = sm;
    float* H1   = sm + 8320;
    float* C0   = sm + 16640;
    float* C1   = sm + 24960;
    uint32_t* WT0 = reinterpret_cast<uint32_t*>(sm + 33280);
    uint32_t* WT1 = reinterpret_cast<uint32_t*>(sm + 41472);
    float* XWV  = sm + 49664;
    float* B1P  = sm + 50688;
    float* XR   = sm + 51712;

    int tid  = threadIdx.x;
    int lane = tid & 31;
    int warp = tid >> 5;            // 0..7, owns N-tiles warp*16..warp*16+15
    int r = lane >> 2;              // fragment row 0..7
    int c = lane & 3;               // fragment col 0..3
    int blk = blockIdx.x;
    int b  = blk >> 3;
    int p0 = (blk & 7) * 32;

    uint32_t wt_base[2];
    wt_base[0] = (uint32_t)__cvta_generic_to_shared(WT0);
    wt_base[1] = (uint32_t)__cvta_generic_to_shared(WT1);

    // ---- init: load particle states (stride-260 layout) ----
    for (int idx = tid; idx < 8192; idx += 256){
        int row = idx >> 8, u = idx & 255; int p = p0 + row;
        size_t base0 = ((size_t)(0*BSC + b)*NHC + u)*NPARTC;
        size_t base1 = ((size_t)(1*BSC + b)*NHC + u)*NPARTC;
        H0[row*HS + u] = particles[base0 + p];
        H1[row*HS + u] = particles[base1 + p];
        C0[row*HS + u] = particles[base0 + MIDP + p];
        C1[row*HS + u] = particles[base1 + MIDP + p];
    }
    for (int jp = tid; jp < 1024; jp += 256){
        int jo = ((jp & 3) << 8) | (jp >> 2);
        B1P[jp] = b1[jo];
    }
    __syncthreads();

    // ---- time loop ----
    for (int t = 0; t < TTC; t++){
        if (tid < 64) XR[tid] = x[(b*TTC + t)*DINC + tid];
        __syncthreads();
        // input projection (permuted j' = 4u+gate), float4-vectorized
        for (int jp = tid; jp < 1024; jp += 256){
            int jo = ((jp & 3) << 8) | (jp >> 2);
            const float4* wr = reinterpret_cast<const float4*>(Wih0 + jo*DINC);
            const float4* xr = reinterpret_cast<const float4*>(XR);
            float acc = b0[jo];
            #pragma unroll
            for (int k4 = 0; k4 < DINC/4; k4++){
                float4 wv = wr[k4]; float4 xv = xr[k4];
                acc = fmaf(xv.x, wv.x, acc);
                acc = fmaf(xv.y, wv.y, acc);
                acc = fmaf(xv.z, wv.z, acc);
                acc = fmaf(xv.w, wv.w, acc);
            }
            XWV[jp] = acc;
        }
        // XWV visibility covered by mainloop barriers below

        for (int layer = 0; layer < 2; layer++){
            float* Hs = (layer==0) ? H0 : H1;
            float* Cs = (layer==0) ? C0 : C1;
            const float* pre = (layer==0) ? XWV : B1P;
            int nkt = (layer==0) ? 32 : 64;                   // 8-k tiles
            int tbase = (layer==0) ? 0 : 32;                  // scratch tile origin

            float4 d4[2][16];
            #pragma unroll
            for (int ms=0; ms<2; ms++)
                #pragma unroll
                for (int j=0; j<16; j++) d4[ms][j] = make_float4(0.f,0.f,0.f,0.f);

            // ---- stage tile 0 into buf 0 (fully coalesced) ----
            {
                const uint32_t* src = scr + (size_t)tbase*8192;
                #pragma unroll
                for (int i=0;i<8;i++){
                    int cidx = i*256 + tid;
                    cp16(wt_base[0] + (uint32_t)cidx*16, src + (size_t)cidx*4);
                }
                asm volatile("cp.async.commit_group;");
            }

            for (int kt = 0; kt < nkt; kt++){
                int pb = kt & 1;
                bool havenext = (kt+1 < nkt);
                if (havenext){
                    const uint32_t* src = scr + (size_t)(tbase + kt + 1)*8192;
                    #pragma unroll
                    for (int i=0;i<8;i++){
                        int cidx = i*256 + tid;
                        cp16(wt_base[pb^1] + (uint32_t)cidx*16, src + (size_t)cidx*4);
                    }
                    asm volatile("cp.async.commit_group;");
                    asm volatile("cp.async.wait_group 1;");
                } else {
                    asm volatile("cp.async.wait_group 0;");
                }
                __syncthreads();   // tile kt data visible to all

                // ---- A fragments (bf16 hi/lo packed) from smem H
                const float* Asrc; int kloc;
                if (layer==0){ Asrc = H0; kloc = kt*8; }
                else if (kt < 32){ Asrc = H0; kloc = kt*8; }
                else { Asrc = H1; kloc = (kt-32)*8; }
                uint32_t a0hi[2], a0lo[2], a1hi[2], a1lo[2];
                #pragma unroll
                for (int ms=0; ms<2; ms++){
                    int row0 = ms*16 + r;
                    float2 av0 = *reinterpret_cast<const float2*>(&Asrc[row0*HS + kloc + 2*c]);
                    float2 av1 = *reinterpret_cast<const float2*>(&Asrc[(row0+8)*HS + kloc + 2*c]);
                    bfsplit2(av0.x, av0.y, a0hi[ms], a0lo[ms]);
                    bfsplit2(av1.x, av1.y, a1hi[ms], a1lo[ms]);
                }
                // ---- mma over owned N-tiles (pre-split B, zero conversions)
                const uint32_t* W = pb ? WT1 : WT0;
                #pragma unroll
                for (int j=0; j<16; j++){
                    int np = (warp*16 + j)*8 + r;
                    uint32_t bhi = W[np*4 + c];
                    uint32_t blo = W[4096 + np*4 + c];
                    #pragma unroll
                    for (int ms=0; ms<2; ms++){
                        mma_bf16(d4[ms][j], a0hi[ms], a1hi[ms], bhi);
                        mma_bf16(d4[ms][j], a0hi[ms], a1hi[ms], blo);
                        mma_bf16(d4[ms][j], a0lo[ms], a1lo[ms], bhi);
                    }
                }
                __syncthreads();   // reads of buf pb done before next overwrite
            }

            // ---- epilogue: add pre-activation, reunite gate quads, cell update
            #pragma unroll
            for (int ms=0; ms<2; ms++){
                #pragma unroll
                for (int j=0; j<16; j++){
                    int nt = warp*16 + j;
                    int jp0 = nt*8 + 2*c;
                    float pz0 = pre[jp0], pz1 = pre[jp0+1];
                    float g0 = d4[ms][j].x + pz0;
                    float g1 = d4[ms][j].y + pz1;
                    float g2 = d4[ms][j].z + pz0;
                    float g3 = d4[ms][j].w + pz1;
                    float e0 = __shfl_xor_sync(0xFFFFFFFFu, g0, 1);
                    float e1 = __shfl_xor_sync(0xFFFFFFFFu, g1, 1);
                    float e2 = __shfl_xor_sync(0xFFFFFFFFu, g2, 1);
                    float e3 = __shfl_xor_sync(0xFFFFFFFFu, g3, 1);
                    if (!(lane & 1)){
                        int u = nt*2 + (c >> 1);
                        int row0 = ms*16 + r;
                        {
                            float cold = Cs[row0*HS + u];
                            float cn = sigf(g1)*cold + sigf(g0)*tanhfa(e0);
                            float hn = sigf(e1)*tanhfa(cn);
                            Cs[row0*HS + u] = cn;
                            Hs[row0*HS + u] = hn;
                        }
                        {
                            float cold = Cs[(row0+8)*HS + u];
                            float cn = sigf(g3)*cold + sigf(g2)*tanhfa(e2);
                            float hn = sigf(e3)*tanhfa(cn);
                            Cs[(row0+8)*HS + u] = cn;
                            Hs[(row0+8)*HS + u] = hn;
                        }
                    }
                }
            }
            __syncthreads();   // H updated before next layer / next t reads
        }
    }

    // ---- all-CTA barrier: weight scratch reads done before pr overwrites it
    __threadfence();
    __syncthreads();
    if (tid == 0){
        unsigned int ticket = atomicAdd(&g_bar, 1u);
        unsigned int target = (ticket/128u + 1u)*128u;
        while ((int)(*(volatile unsigned int*)&g_bar - target) < 0) { }
    }
    __syncthreads();

    // ---- write pr = final state + noise into pf (l,b,u,512) ----
    float sq = sqrtf(q[0]*q[0]);
    float se = sqrtf(e[0]*e[0]);
    for (int idx = tid; idx < 8192; idx += 256){
        int row = idx >> 8, u = idx & 255; int p = p0 + row;
        size_t o0 = ((size_t)(0*BSC + b)*NHC + u)*NPARTC;
        size_t o1 = ((size_t)(1*BSC + b)*NHC + u)*NPARTC;
        int e0i = ((p*LSC + 0)*BSC + b)*NHC + u;
        int e1i = ((p*LSC + 1)*BSC + b)*NHC + u;
        pf[o0 + p]        = H0[row*HS+u] + sq*eps_h[e0i];
        pf[o1 + p]        = H1[row*HS+u] + sq*eps_h[e1i];
        pf[o0 + MIDP + p] = C0[row*HS+u] + se*eps_c[e0i];
        pf[o1 + MIDP + p] = C1[row*HS+u] + se*eps_c[e1i];
    }
}

// ---------------- obs + weight update; preW staged into out.wf ---------------
__global__ __launch_bounds__(512)
void k_stats1(const float* __restrict__ weights, const float* __restrict__ y,
              const float* __restrict__ r, const float* __restrict__ pf,
              const float* __restrict__ Wh, const float* __restrict__ bh,
              float* __restrict__ out){
    __shared__ __align__(16) float ws[NHC];
    __shared__ float red[512];
    int b = blockIdx.x; int tid = threadIdx.x;
    if (tid < NHC) ws[tid] = Wh[tid];
    __syncthreads();
    float Yv = bh[0];
    const float* base = pf + ((size_t)(BSC + b)*NHC)*NPARTC;   // l=1
    for (int u=0; u<NHC; u++) Yv = fmaf(ws[u], base[(size_t)u*NPARTC + tid], Yv);
    float w  = logf(weights[b*NPARTC + tid]);
    float wsum = bsum(red, tid, 512, w);
    float s1   = bsum(red, tid, 512, Yv*w);
    float Wmu  = s1 / wsum;
    float cen  = Yv - Wmu;
    float cov  = bsum(red, tid, 512, cen*cen) / (float)(NPARTC-1) + r[0]*r[0];
    float s    = cov + 1e-6f;
    float innov = y[b] - Yv*w/wsum;
    out[OFF_WF + b*NPARTC + tid] = w - 0.5f*logf(s) - 0.5f*innov*innov/s;   // preW
}

// ---- normalize preW across the BATCH axis (reference quirk), in place -------
__global__ __launch_bounds__(512)
void k_norm(float* __restrict__ out){
    int n = threadIdx.x;
    float v[BSC];
    float s = 0.0f;
    #pragma unroll
    for (int b=0;b<BSC;b++){ v[b] = out[OFF_WF + b*NPARTC + n]; s += expf(v[b]); }
    float ls = logf(s);
    #pragma unroll
    for (int b=0;b<BSC;b++) out[OFF_WF + b*NPARTC + n] = expf(v[b] - ls);   // neww
}

// ---------------- per-(batch,half) resample: bitonic argsort of 256 ----------
__global__ __launch_bounds__(256)
void k_resample(const float* __restrict__ gumbel, float* __restrict__ out){
    __shared__ __align__(16) float key[256];
    __shared__ __align__(16) int   idxs[256];
    __shared__ __align__(16) float red[256];
    int blk = blockIdx.x; int b = blk>>1; int half = blk&1; int tid = threadIdx.x;
    float wh = out[OFF_WF + b*NPARTC + half*MIDP + tid];
    float ss = bsum(red, tid, 256, wh*wh);
    int dof = (1.0f/ss < (float)NPARTC/4.0f) ? 1 : 0;
    float soft = 0.5f*wh + 0.5f/(float)MIDP;
    key[tid]  = -(logf(soft) + gumbel[(b*2 + half)*MIDP + tid]);
    idxs[tid] = tid;
    __syncthreads();
    for (int k=2;k<=256;k<<=1){
        for (int j=k>>1;j>0;j>>=1){
            int ixj = tid ^ j;
            if (ixj > tid){
                bool up = ((tid & k) == 0);
                float a = key[tid], bk = key[ixj];
                if ((a > bk) == up){
                    key[tid]=bk; key[ixj]=a;
                    int t0=idxs[tid]; idxs[tid]=idxs[ixj]; idxs[ixj]=t0;
                }
            }
            __syncthreads();
        }
    }
    g_idx[blk*MIDP + tid] = idxs[tid];
    float lw = logf(wh/soft);
    float mx = bmax(red, tid, 256, lw);
    float se = bsum(red, tid, 256, expf(lw-mx));
    float lse = mx + logf(se);
    float wr = expf(lw - lse);
    out[OFF_WF + b*NPARTC + half*MIDP + tid] = dof ? wr : wh;
    if (tid==0) g_do[blk] = dof;
}

// ---------------- in-place gather on pf (per (b,half) permutation) -----------
__global__ __launch_bounds__(256)
void k_gather(float* __restrict__ pf){
    __shared__ __align__(16) float seg[8][256];
    __shared__ int idx_s[256];
    int blk = blockIdx.x;            // b*2+half
    int chunk = blockIdx.y;          // 0..63 -> 8 (l,u) rows each
    int b = blk>>1; int half = blk&1; int tid = threadIdx.x;
    if (!g_do[blk]) return;
    idx_s[tid] = g_idx[blk*MIDP + tid];
    int row0 = chunk*8;
    #pragma unroll
    for (int i=0;i<8;i++){
        int rr = row0 + i;
        int l = rr >> 8, u = rr & 255;
        seg[i][tid] = pf[(((size_t)(l*BSC+b))*NHC + u)*NPARTC + half*MIDP + tid];
    }
    __syncthreads();
    #pragma unroll
    for (int i=0;i<8;i++){
        int rr = row0 + i;
        int l = rr >> 8, u = rr & 255;
        pf[(((size_t)(l*BSC+b))*NHC + u)*NPARTC + half*MIDP + tid] = seg[i][idx_s[tid]];
    }
}

// ---------------- final estimate (obs fused, 16 blocks) ----------------------
__global__ __launch_bounds__(512)
void k_stats2(const float* __restrict__ y, const float* __restrict__ r,
              const float* __restrict__ pf, const float* __restrict__ Wh,
              const float* __restrict__ bh, float* __restrict__ out){
    __shared__ __align__(16) float ws[NHC];
    __shared__ float red[512];
    int b = blockIdx.x; int tid = threadIdx.x;
    if (tid < NHC) ws[tid] = Wh[tid];
    __syncthreads();
    float Yv = bh[0];
    const float* base = pf + ((size_t)(BSC + b)*NHC)*NPARTC;   // l=1
    for (int u=0; u<NHC; u++) Yv = fmaf(ws[u], base[(size_t)u*NPARTC + tid], Yv);
    float wv = out[OFF_WF + b*NPARTC + tid];
    float wsum = bsum(red, tid, 512, wv);
    float Wmu  = bsum(red, tid, 512, Yv*wv) / wsum;
    float cen  = Yv - Wmu;
    float cov  = bsum(red, tid, 512, cen*cen) / (float)(NPARTC-1) + r[0]*r[0];
    if (tid==0){
        out[OFF_WMU + b] = Wmu;
        out[OFF_SIG + b] = cov;
    }
}

// ---- scalars recomputed from already-written W_mu/sig -----------------------
__global__ __launch_bounds__(32)
void k_scalars(const float* __restrict__ y, float* __restrict__ out){
    if (threadIdx.x != 0) return;
    float l = 0.0f, nq = 0.0f;
    for (int b=0;b<BSC;b++){
        float s = out[OFF_SIG + b] + 1e-6f;
        float inn = y[b] - out[OFF_WMU + b];
        float qf = inn*inn/s;
        l += -0.5f*logf(s) - 0.5f*qf;
        nq += qf;
    }
    out[OFF_L]   = l;
    out[OFF_NIS] = nq / (float)BSC;
}

// =============================================================================
extern "C" void kernel_launch(void* const* d_in, const int* in_sizes, int n_in,
                              void* d_out, int out_size){
    const float* x        = (const float*)d_in[0];
    const float* y        = (const float*)d_in[1];
    const float* particles= (const float*)d_in[2];
    const float* weights  = (const float*)d_in[3];
    const float* q        = (const float*)d_in[4];
    const float* e        = (const float*)d_in[5];
    const float* r        = (const float*)d_in[6];
    const float* Wih0     = (const float*)d_in[7];
    const float* Whh0     = (const float*)d_in[8];
    const float* b0       = (const float*)d_in[9];
    const float* Wih1     = (const float*)d_in[10];
    const float* Whh1     = (const float*)d_in[11];
    const float* b1       = (const float*)d_in[12];
    const float* Wh       = (const float*)d_in[13];
    const float* bh       = (const float*)d_in[14];
    const float* eps_h    = (const float*)d_in[15];
    const float* eps_c    = (const float*)d_in[16];
    const float* gumbel   = (const float*)d_in[17];
    float* out = (float*)d_out;
    float* pf  = out + OFF_PF;
    uint32_t* scr = (uint32_t*)pf;      // 3 MB weight scratch inside pf

    static bool attr_set = false;
    if (!attr_set){
        cudaFuncSetAttribute(k_lstm, cudaFuncAttributeMaxDynamicSharedMemorySize, SMEM_BYTES);
        attr_set = true;
    }

    // 0. pre-split weights into bf16 hi/lo tile images (scratch in pf)
    k_prep<<<96, 256>>>(Whh0, Wih1, Whh1, scr);
    // 1. full recurrence (tensor-core 3x bf16, coalesced cp.async staging)
    k_lstm<<<128, 256, SMEM_BYTES>>>(x, particles, q, e, Wih0, b0, b1,
                                     eps_h, eps_c, scr, pf);
    // 2. obs + weight update (preW -> out.wf), batch-axis norm in place
    k_stats1<<<BSC, 512>>>(weights, y, r, pf, Wh, bh, out);
    k_norm<<<1, 512>>>(out);
    // 3. resample halves (reads neww from out.wf, writes final wf + g_idx/g_do)
    k_resample<<<BSC*2, 256>>>(gumbel, out);
    // 4. in-place gather pr -> pf
    k_gather<<<dim3(BSC*2, 64), 256>>>(pf);
    // 5. final obs + estimate, then scalars
    k_stats2<<<BSC, 512>>>(y, r, pf, Wh, bh, out);
    k_scalars<<<1, 32>>>(y, out);
}